// round 1
// baseline (speedup 1.0000x reference)
#include <cuda_runtime.h>
#include <math.h>

#define BB 2
#define NN 384
#define CS 256
#define CZ 128
#define NODE_IN_K 145
#define EDGE_IN_K 200
#define NODE_ELEMS (BB*NN*CS)

#define EDGE_AS 201   // A stride (floats) for edge tile (K=200 + 1)
#define EDGE_HS 132   // H stride for edge (128 + 4)
#define NODE_AS 152   // A stride for node (K padded 145->152)
#define NODE_HS 260   // H stride for node (256 + 4)

#define NODE_BLOCKS 12                 // 768 rows / 64
#define EDGE_BLOCKS (BB*NN*(NN/128))   // 2304

// smem (floats): edge: A 128*201=25728 | H1 128*132=16896 | W 1024  => 43648
//                node: A 64*152=9728 | H1 64*260=16640 | H2 16640 | W 2048 => 45056
#define SMEM_FLOATS 45056
#define SMEM_BYTES  (SMEM_FLOATS*4)

__device__ float g_pt[BB*NN*73];
__device__ float g_node_in[BB*NN*NODE_IN_K];

// ---------------------------------------------------------------------------
// Kernel 1: per-residue features (prot_t_embed 73, node_in 145)
// ---------------------------------------------------------------------------
__global__ void feat_kernel(const float* __restrict__ noised,
                            const int*   __restrict__ seq,
                            const float* __restrict__ tarr,
                            const float* __restrict__ fmask,
                            const float* __restrict__ trans,
                            const float* __restrict__ rots,
                            const float* __restrict__ atom14)
{
    int u = blockIdx.x * blockDim.x + threadIdx.x;
    if (u >= BB*NN) return;
    int b = u / NN;
    float* pt = g_pt + u*73;
    float* ni = g_node_in + u*NODE_IN_K;

    // timestep embedding
    float tv = tarr[b] * 10000.0f;
    const float c1 = (float)(-9.210340371976184/15.0);   // -ln(10000)/15
    #pragma unroll
    for (int h = 0; h < 16; h++) {
        float fr = expf((float)h * c1);
        float s, c;
        sincosf(tv * fr, &s, &c);
        pt[h] = s; pt[16+h] = c;
    }
    pt[32] = fmask[u];
    const float* na = noised + u*30;
    #pragma unroll
    for (int m = 0; m < 30; m++) pt[33+m] = na[m];
    #pragma unroll
    for (int a = 0; a < 10; a++) {
        float x = na[a*3], y = na[a*3+1], z = na[a*3+2];
        pt[63+a] = 1.0f / (1.0f + (x*x + y*y + z*z));
    }

    // node_in = [pt(73), idx_emb(32), local(30), 1/(1+|local|)(10)]
    for (int k = 0; k < 73; k++) ni[k] = pt[k];
    float sif = (float)seq[u];
    #pragma unroll
    for (int kk = 0; kk < 16; kk++) {
        float denom = powf(2056.0f, (float)kk * (1.0f/16.0f));
        float s, c;
        sincosf(sif * 3.14159265358979f / denom, &s, &c);
        ni[73+kk] = s; ni[89+kk] = c;
    }
    const float* R = rots + u*9;
    float t0 = trans[u*3], t1 = trans[u*3+1], t2 = trans[u*3+2];
    #pragma unroll
    for (int a = 0; a < 10; a++) {
        const float* at = atom14 + u*42 + (4+a)*3;
        float vx = at[0]-t0, vy = at[1]-t1, vz = at[2]-t2;
        float l0 = R[0]*vx + R[3]*vy + R[6]*vz;   // local[a][i] = sum_j R[j][i] v[j]
        float l1 = R[1]*vx + R[4]*vy + R[7]*vz;
        float l2 = R[2]*vx + R[5]*vy + R[8]*vz;
        ni[105+a*3+0] = l0; ni[105+a*3+1] = l1; ni[105+a*3+2] = l2;
        ni[135+a] = 1.0f/(1.0f + sqrtf(l0*l0 + l1*l1 + l2*l2));
    }
}

// ---------------------------------------------------------------------------
// Fused MLP helpers
// ---------------------------------------------------------------------------
__device__ __forceinline__ void zero_acc(float acc[8][8]) {
    #pragma unroll
    for (int r = 0; r < 8; r++)
        #pragma unroll
        for (int c = 0; c < 8; c++) acc[r][c] = 0.0f;
}

__device__ __forceinline__ void ld8(float* d, const float* __restrict__ s) {
    *(float4*)d       = *(const float4*)s;
    *(float4*)(d + 4) = *(const float4*)(s + 4);
}

// Tiled GEMM accumulate: acc[8][8] += A[ty*8+rr][k] * W[k][tx*8+cc]
// A in smem ([row][k], arbitrary stride), W streamed from gmem in 8-row chunks.
template<int TN>
__device__ __forceinline__ void mlp_gemm(float acc[8][8],
    const float* Asm, int astride,
    const float* __restrict__ Wg, int Kpad, int Kreal,
    float* Wsm, int tid, int ty, int tx)
{
    #pragma unroll 1
    for (int k0 = 0; k0 < Kpad; k0 += 8) {
        __syncthreads();                       // prior chunk consumed / A ready
        constexpr int PER = (8*TN)/256;        // floats per thread (4 or 8)
        #pragma unroll
        for (int v = 0; v < PER/4; v++) {
            int e = tid*PER + v*4;
            int k = k0 + e / TN;
            float4 val = make_float4(0.f, 0.f, 0.f, 0.f);
            if (k < Kreal) val = *(const float4*)(Wg + k*TN + (e & (TN-1)));
            *(float4*)(Wsm + e) = val;
        }
        __syncthreads();
        #pragma unroll
        for (int kk = 0; kk < 8; kk++) {
            float bv[8];
            *(float4*)(bv)     = *(const float4*)(Wsm + kk*TN + tx*8);
            *(float4*)(bv + 4) = *(const float4*)(Wsm + kk*TN + tx*8 + 4);
            #pragma unroll
            for (int rr = 0; rr < 8; rr++) {
                float a = Asm[(ty*8+rr)*astride + k0 + kk];
                #pragma unroll
                for (int cc = 0; cc < 8; cc++)
                    acc[rr][cc] = fmaf(a, bv[cc], acc[rr][cc]);
            }
        }
    }
}

__device__ __forceinline__ void store_relu(float* H, int hs,
    const float bias[8], float acc[8][8], int ty, int tx)
{
    #pragma unroll
    for (int rr = 0; rr < 8; rr++) {
        float4 v0, v1;
        v0.x = fmaxf(acc[rr][0] + bias[0], 0.f);
        v0.y = fmaxf(acc[rr][1] + bias[1], 0.f);
        v0.z = fmaxf(acc[rr][2] + bias[2], 0.f);
        v0.w = fmaxf(acc[rr][3] + bias[3], 0.f);
        v1.x = fmaxf(acc[rr][4] + bias[4], 0.f);
        v1.y = fmaxf(acc[rr][5] + bias[5], 0.f);
        v1.z = fmaxf(acc[rr][6] + bias[6], 0.f);
        v1.w = fmaxf(acc[rr][7] + bias[7], 0.f);
        *(float4*)(H + (ty*8+rr)*hs + tx*8)     = v0;
        *(float4*)(H + (ty*8+rr)*hs + tx*8 + 4) = v1;
    }
}

template<int RED>
__device__ __forceinline__ float warp_red(float v) {
    #pragma unroll
    for (int m = RED; m >= 1; m >>= 1) v += __shfl_xor_sync(0xffffffffu, v, m);
    return v;
}

// ---------------------------------------------------------------------------
// Fused node+edge MLP kernel. Blocks [0,12) = node MLP, [12, 12+2304) = edge.
// ---------------------------------------------------------------------------
__global__ void __launch_bounds__(256, 1)
mlp_kernel(const int* __restrict__ seq, const float* __restrict__ trans,
           const float* __restrict__ nw1, const float* __restrict__ nb1,
           const float* __restrict__ nw2, const float* __restrict__ nb2,
           const float* __restrict__ nw3, const float* __restrict__ nb3,
           const float* __restrict__ ng,  const float* __restrict__ nbt,
           const float* __restrict__ ew1, const float* __restrict__ eb1,
           const float* __restrict__ ew2, const float* __restrict__ eb2,
           const float* __restrict__ ew3, const float* __restrict__ eb3,
           const float* __restrict__ eg,  const float* __restrict__ ebt,
           float* __restrict__ out)
{
    extern __shared__ float sm[];
    int tid = threadIdx.x;

    if (blockIdx.x < NODE_BLOCKS) {
        // ----------------------------- NODE PATH ---------------------------
        float* A  = sm;                    // 64 x NODE_AS
        float* H1 = A  + 64*NODE_AS;       // 64 x NODE_HS
        float* H2 = H1 + 64*NODE_HS;       // 64 x NODE_HS
        float* W  = H2 + 64*NODE_HS;       // 8 x 256
        int row0 = blockIdx.x * 64;
        int tx = tid & 31, ty = tid >> 5;  // 32 col-groups x 8 row-groups

        for (int e = tid; e < 64*NODE_AS; e += 256) {
            int r = e / NODE_AS, k = e - r*NODE_AS;
            A[e] = (k < NODE_IN_K) ? g_node_in[(row0+r)*NODE_IN_K + k] : 0.0f;
        }

        float acc[8][8];
        zero_acc(acc);
        mlp_gemm<256>(acc, A, NODE_AS, nw1, 152, 145, W, tid, ty, tx);
        { float b[8]; ld8(b, nb1 + tx*8); store_relu(H1, NODE_HS, b, acc, ty, tx); }

        zero_acc(acc);
        mlp_gemm<256>(acc, H1, NODE_HS, nw2, 256, 256, W, tid, ty, tx);
        { float b[8]; ld8(b, nb2 + tx*8); store_relu(H2, NODE_HS, b, acc, ty, tx); }

        zero_acc(acc);
        mlp_gemm<256>(acc, H2, NODE_HS, nw3, 256, 256, W, tid, ty, tx);

        float b3[8], gv[8], btv[8];
        ld8(b3, nb3 + tx*8); ld8(gv, ng + tx*8); ld8(btv, nbt + tx*8);
        #pragma unroll
        for (int rr = 0; rr < 8; rr++) {
            float v[8], s = 0.f;
            #pragma unroll
            for (int cc = 0; cc < 8; cc++) { v[cc] = acc[rr][cc] + b3[cc]; s += v[cc]; }
            s = warp_red<16>(s);                 // 32-lane reduce
            float mu = s * (1.0f/256.0f);
            float q = 0.f;
            #pragma unroll
            for (int cc = 0; cc < 8; cc++) { float d = v[cc]-mu; q += d*d; }
            q = warp_red<16>(q);
            float rstd = rsqrtf(q * (1.0f/256.0f) + 1e-5f);
            float o[8];
            #pragma unroll
            for (int cc = 0; cc < 8; cc++) o[cc] = (v[cc]-mu)*rstd*gv[cc] + btv[cc];
            float* op = out + (size_t)(row0 + ty*8 + rr)*CS + tx*8;
            *(float4*)op       = *(float4*)o;
            *(float4*)(op + 4) = *(float4*)(o + 4);
        }
    } else {
        // ----------------------------- EDGE PATH ---------------------------
        int ebk = blockIdx.x - NODE_BLOCKS;
        int b   = ebk / (NN*3);
        int rem = ebk % (NN*3);
        int i   = rem / 3;
        int j0  = (rem % 3) * 128;

        float* A  = sm;                    // 128 x EDGE_AS (also H2 region)
        float* H1 = A + 128*EDGE_AS;       // 128 x EDGE_HS
        float* W  = H1 + 128*EDGE_HS;      // 8 x 128
        float* H2 = sm;                    // stride EDGE_HS, overlays A
        int tx = tid & 15, ty = tid >> 4;  // 16 col-groups x 16 row-groups

        // ---- build edge_in tile [128 rows (j), 200 features] in smem ----
        {
            int r = tid & 127, half = tid >> 7;
            int j = j0 + r;
            const float* pti = g_pt + (size_t)(b*NN + i)*73;
            const float* ptj = g_pt + (size_t)(b*NN + j)*73;
            float* Ar = A + r*EDGE_AS;
            if (half == 0) {
                for (int k = 0; k < 73; k++)  Ar[k] = pti[k];
                for (int k = 73; k < 100; k++) Ar[k] = ptj[k-73];
            } else {
                for (int k = 100; k < 146; k++) Ar[k] = ptj[k-73];
                float rel = (float)(seq[b*NN+i] - seq[b*NN+j]);
                #pragma unroll
                for (int kk = 0; kk < 16; kk++) {
                    float denom = powf(2056.0f, (float)kk * (1.0f/16.0f));
                    float s, c;
                    sincosf(rel * 3.14159265358979f / denom, &s, &c);
                    Ar[146+kk] = s; Ar[162+kk] = c;
                }
                float dx = trans[(b*NN+i)*3+0] - trans[(b*NN+j)*3+0];
                float dy = trans[(b*NN+i)*3+1] - trans[(b*NN+j)*3+1];
                float dz = trans[(b*NN+i)*3+2] - trans[(b*NN+j)*3+2];
                float d = sqrtf(dx*dx + dy*dy + dz*dz);
                const float step = (20.0f - 1e-5f) / 21.0f;
                #pragma unroll
                for (int t = 0; t < 22; t++) {
                    float lo = 1e-5f + (float)t * step;
                    float up = (t < 21) ? (1e-5f + (float)(t+1)*step) : 1e8f;
                    Ar[178+t] = (d > lo && d < up) ? 1.0f : 0.0f;
                }
            }
        }

        float acc[8][8];
        zero_acc(acc);
        mlp_gemm<128>(acc, A, EDGE_AS, ew1, 200, 200, W, tid, ty, tx);
        { float bb[8]; ld8(bb, eb1 + tx*8); store_relu(H1, EDGE_HS, bb, acc, ty, tx); }

        zero_acc(acc);
        mlp_gemm<128>(acc, H1, EDGE_HS, ew2, 128, 128, W, tid, ty, tx);
        { float bb[8]; ld8(bb, eb2 + tx*8); store_relu(H2, EDGE_HS, bb, acc, ty, tx); }

        zero_acc(acc);
        mlp_gemm<128>(acc, H2, EDGE_HS, ew3, 128, 128, W, tid, ty, tx);

        float b3[8], gv[8], btv[8];
        ld8(b3, eb3 + tx*8); ld8(gv, eg + tx*8); ld8(btv, ebt + tx*8);
        float* oe = out + NODE_ELEMS + ((size_t)(b*NN + i)*NN + j0)*CZ;
        #pragma unroll
        for (int rr = 0; rr < 8; rr++) {
            float v[8], s = 0.f;
            #pragma unroll
            for (int cc = 0; cc < 8; cc++) { v[cc] = acc[rr][cc] + b3[cc]; s += v[cc]; }
            s = warp_red<8>(s);                  // 16-lane (half-warp) reduce
            float mu = s * (1.0f/128.0f);
            float q = 0.f;
            #pragma unroll
            for (int cc = 0; cc < 8; cc++) { float d = v[cc]-mu; q += d*d; }
            q = warp_red<8>(q);
            float rstd = rsqrtf(q * (1.0f/128.0f) + 1e-5f);
            float o[8];
            #pragma unroll
            for (int cc = 0; cc < 8; cc++) o[cc] = (v[cc]-mu)*rstd*gv[cc] + btv[cc];
            float* op = oe + (size_t)(ty*8 + rr)*CZ + tx*8;
            *(float4*)op       = *(float4*)o;
            *(float4*)(op + 4) = *(float4*)(o + 4);
        }
    }
}

// ---------------------------------------------------------------------------
extern "C" void kernel_launch(void* const* d_in, const int* in_sizes, int n_in,
                              void* d_out, int out_size)
{
    const float* noised = (const float*)d_in[0];
    const int*   seq    = (const int*)  d_in[1];
    const float* t      = (const float*)d_in[2];
    const float* fmask  = (const float*)d_in[3];
    // d_in[4] = node_mask (unused by reference)
    const float* trans  = (const float*)d_in[5];
    const float* rots   = (const float*)d_in[6];
    const float* atom14 = (const float*)d_in[7];
    const float* nw1 = (const float*)d_in[8];
    const float* nb1 = (const float*)d_in[9];
    const float* nw2 = (const float*)d_in[10];
    const float* nb2 = (const float*)d_in[11];
    const float* nw3 = (const float*)d_in[12];
    const float* nb3 = (const float*)d_in[13];
    const float* ng  = (const float*)d_in[14];
    const float* nbt = (const float*)d_in[15];
    const float* ew1 = (const float*)d_in[16];
    const float* eb1 = (const float*)d_in[17];
    const float* ew2 = (const float*)d_in[18];
    const float* eb2 = (const float*)d_in[19];
    const float* ew3 = (const float*)d_in[20];
    const float* eb3 = (const float*)d_in[21];
    const float* eg  = (const float*)d_in[22];
    const float* ebt = (const float*)d_in[23];
    float* out = (float*)d_out;

    cudaFuncSetAttribute(mlp_kernel,
                         cudaFuncAttributeMaxDynamicSharedMemorySize, SMEM_BYTES);

    feat_kernel<<<6, 128>>>(noised, seq, t, fmask, trans, rots, atom14);
    mlp_kernel<<<NODE_BLOCKS + EDGE_BLOCKS, 256, SMEM_BYTES>>>(
        seq, trans,
        nw1, nb1, nw2, nb2, nw3, nb3, ng, nbt,
        ew1, eb1, ew2, eb2, ew3, eb3, eg, ebt,
        out);
}

// round 3
// speedup vs baseline: 1.4035x; 1.4035x over previous
#include <cuda_runtime.h>
#include <math.h>
#include <stdint.h>

#define BB 2
#define NN 384
#define CS 256
#define CZ 128
#define NODE_IN_K 145
#define NODE_ELEMS (BB*NN*CS)

#define NODE_AS 152
#define NODE_HS 260

#define NODE_BLOCKS 12
#define EDGE_BLOCKS (BB*NN*(NN/128))   // 2304

#define SA 204                 // A smem stride (floats): conflict-free for frag loads
#define SB 132                 // B smem stride (floats): conflict-free for frag loads
#define A_FLOATS (128*SA)      // 26112
#define B_FLOATS (200*SB)      // 26400
#define RED_OFF  (A_FLOATS + B_FLOATS)
#define EDGE_SMEM_FLOATS (RED_OFF + 512)
#define SMEM_BYTES (EDGE_SMEM_FLOATS*4)   // 212096 B (node path needs 180224)

__device__ float g_pt[BB*NN*73];
__device__ float g_node_in[BB*NN*NODE_IN_K];
__device__ __align__(16) float gB1p[200*SB];   // ew1 padded [k][n], fp32
__device__ __align__(16) float gB2p[128*SB];
__device__ __align__(16) float gB3p[128*SB];

// ---------------------------------------------------------------------------
__device__ __forceinline__ uint32_t s2u(const void* p){
    uint32_t a;
    asm("{ .reg .u64 t; cvta.to.shared.u64 t, %1; cvt.u32.u64 %0, t; }":"=r"(a):"l"(p));
    return a;
}
__device__ __forceinline__ void split_tf32(float x, uint32_t& hi, uint32_t& lo){
    uint32_t h; asm("cvt.rna.tf32.f32 %0, %1;":"=r"(h):"f"(x));
    hi = h;
    lo = __float_as_uint(x - __uint_as_float(h));   // HW truncates low bits: fine
}
__device__ __forceinline__ void mma8(float c[4], const uint32_t a[4], uint32_t b0, uint32_t b1){
    asm volatile(
        "mma.sync.aligned.m16n8k8.row.col.f32.tf32.tf32.f32 "
        "{%0,%1,%2,%3}, {%4,%5,%6,%7}, {%8,%9}, {%0,%1,%2,%3};"
        : "+f"(c[0]),"+f"(c[1]),"+f"(c[2]),"+f"(c[3])
        : "r"(a[0]),"r"(a[1]),"r"(a[2]),"r"(a[3]),"r"(b0),"r"(b1));
}
__device__ __forceinline__ void cpa(float* dsm, const float* g, int bytes, int tid, int nt){
    uint32_t d = s2u(dsm);
    for (int o = tid*16; o < bytes; o += nt*16)
        asm volatile("cp.async.cg.shared.global [%0], [%1], 16;"
                     ::"r"(d+o),"l"((const char*)g+o):"memory");
    asm volatile("cp.async.commit_group;":::"memory");
}
#define CP_WAIT() asm volatile("cp.async.wait_group 0;":::"memory")

__device__ __forceinline__ void zacc(float acc[2][8][4]){
    #pragma unroll
    for (int m = 0; m < 2; m++)
        #pragma unroll
        for (int n = 0; n < 8; n++)
            #pragma unroll
            for (int q = 0; q < 4; q++) acc[m][n][q] = 0.0f;
}

// compensated tf32 GEMM: acc += A[128xK] * B[Kx128], 3 mma passes
template<int KSTEPS>
__device__ __forceinline__ void gemm3p(const float* __restrict__ A,
                                       const float* __restrict__ B,
                                       float acc[2][8][4], int lane, int wr, int wc)
{
    const float* ap = A + (wr*32 + (lane>>2))*SA + (lane&3);
    const float* bp = B + (lane&3)*SB + wc*64 + (lane>>2);
    #pragma unroll 1
    for (int ks = 0; ks < KSTEPS; ks++){
        const float* a0p = ap + ks*8;
        const float* b0p = bp + ks*8*SB;
        uint32_t ah[2][4], al[2][4];
        #pragma unroll
        for (int mt = 0; mt < 2; mt++){
            split_tf32(a0p[ mt*16   *SA    ], ah[mt][0], al[mt][0]);
            split_tf32(a0p[(mt*16+8)*SA    ], ah[mt][1], al[mt][1]);
            split_tf32(a0p[ mt*16   *SA + 4], ah[mt][2], al[mt][2]);
            split_tf32(a0p[(mt*16+8)*SA + 4], ah[mt][3], al[mt][3]);
        }
        #pragma unroll
        for (int nt = 0; nt < 8; nt++){
            uint32_t bh0, bl0, bh1, bl1;
            split_tf32(b0p[nt*8       ], bh0, bl0);
            split_tf32(b0p[nt*8 + 4*SB], bh1, bl1);
            #pragma unroll
            for (int mt = 0; mt < 2; mt++){
                mma8(acc[mt][nt], ah[mt], bh0, bh1);
                mma8(acc[mt][nt], al[mt], bh0, bh1);
                mma8(acc[mt][nt], ah[mt], bl0, bl1);
            }
        }
    }
}

// epilogue: H = relu(acc + bias) -> A region (fp32)
__device__ __forceinline__ void epi_store(float* A, const float* __restrict__ bias,
                                          float acc[2][8][4], int lane, int wr, int wc)
{
    int r  = wr*32 + (lane>>2);
    int cb = wc*64 + (lane&3)*2;
    #pragma unroll
    for (int nt = 0; nt < 8; nt++){
        float2 bv = *(const float2*)(bias + cb + nt*8);
        #pragma unroll
        for (int mt = 0; mt < 2; mt++){
            float v0 = fmaxf(acc[mt][nt][0] + bv.x, 0.f);
            float v1 = fmaxf(acc[mt][nt][1] + bv.y, 0.f);
            float v2 = fmaxf(acc[mt][nt][2] + bv.x, 0.f);
            float v3 = fmaxf(acc[mt][nt][3] + bv.y, 0.f);
            *(float2*)(A + (r+mt*16  )*SA + cb + nt*8) = make_float2(v0, v1);
            *(float2*)(A + (r+mt*16+8)*SA + cb + nt*8) = make_float2(v2, v3);
        }
    }
}

// ---------------------------------------------------------------------------
// Kernel 1: per-residue features
// ---------------------------------------------------------------------------
__global__ void feat_kernel(const float* __restrict__ noised,
                            const int*   __restrict__ seq,
                            const float* __restrict__ tarr,
                            const float* __restrict__ fmask,
                            const float* __restrict__ trans,
                            const float* __restrict__ rots,
                            const float* __restrict__ atom14)
{
    int u = blockIdx.x * blockDim.x + threadIdx.x;
    if (u >= BB*NN) return;
    int b = u / NN;
    float* pt = g_pt + u*73;
    float* ni = g_node_in + u*NODE_IN_K;

    float tv = tarr[b] * 10000.0f;
    const float c1 = (float)(-9.210340371976184/15.0);
    #pragma unroll
    for (int h = 0; h < 16; h++) {
        float fr = expf((float)h * c1);
        float s, c;
        sincosf(tv * fr, &s, &c);
        pt[h] = s; pt[16+h] = c;
    }
    pt[32] = fmask[u];
    const float* na = noised + u*30;
    #pragma unroll
    for (int m = 0; m < 30; m++) pt[33+m] = na[m];
    #pragma unroll
    for (int a = 0; a < 10; a++) {
        float x = na[a*3], y = na[a*3+1], z = na[a*3+2];
        pt[63+a] = 1.0f / (1.0f + (x*x + y*y + z*z));
    }

    for (int k = 0; k < 73; k++) ni[k] = pt[k];
    float sif = (float)seq[u];
    #pragma unroll
    for (int kk = 0; kk < 16; kk++) {
        float denom = powf(2056.0f, (float)kk * (1.0f/16.0f));
        float s, c;
        sincosf(sif * 3.14159265358979f / denom, &s, &c);
        ni[73+kk] = s; ni[89+kk] = c;
    }
    const float* R = rots + u*9;
    float t0 = trans[u*3], t1 = trans[u*3+1], t2 = trans[u*3+2];
    #pragma unroll
    for (int a = 0; a < 10; a++) {
        const float* at = atom14 + u*42 + (4+a)*3;
        float vx = at[0]-t0, vy = at[1]-t1, vz = at[2]-t2;
        float l0 = R[0]*vx + R[3]*vy + R[6]*vz;
        float l1 = R[1]*vx + R[4]*vy + R[7]*vz;
        float l2 = R[2]*vx + R[5]*vy + R[8]*vz;
        ni[105+a*3+0] = l0; ni[105+a*3+1] = l1; ni[105+a*3+2] = l2;
        ni[135+a] = 1.0f/(1.0f + sqrtf(l0*l0 + l1*l1 + l2*l2));
    }
}

// ---------------------------------------------------------------------------
// Kernel 2: pad edge weights to stride-132 [k][n] fp32
// ---------------------------------------------------------------------------
__global__ void wprep_kernel(const float* __restrict__ ew1,
                             const float* __restrict__ ew2,
                             const float* __restrict__ ew3)
{
    int t = blockIdx.x*blockDim.x + threadIdx.x;
    int nt = gridDim.x*blockDim.x;
    for (int idx = t; idx < 200*SB; idx += nt) {
        int k = idx / SB, n = idx % SB;
        gB1p[idx] = (n < 128) ? ew1[k*128 + n] : 0.0f;
    }
    for (int idx = t; idx < 128*SB; idx += nt) {
        int k = idx / SB, n = idx % SB;
        gB2p[idx] = (n < 128) ? ew2[k*128 + n] : 0.0f;
        gB3p[idx] = (n < 128) ? ew3[k*128 + n] : 0.0f;
    }
}

// ---------------------------------------------------------------------------
// FFMA node-path helpers (R1, passing)
// ---------------------------------------------------------------------------
__device__ __forceinline__ void zero_acc(float acc[8][8]) {
    #pragma unroll
    for (int r = 0; r < 8; r++)
        #pragma unroll
        for (int c = 0; c < 8; c++) acc[r][c] = 0.0f;
}
__device__ __forceinline__ void ld8(float* d, const float* __restrict__ s) {
    *(float4*)d       = *(const float4*)s;
    *(float4*)(d + 4) = *(const float4*)(s + 4);
}
template<int TN>
__device__ __forceinline__ void mlp_gemm(float acc[8][8],
    const float* Asm, int astride,
    const float* __restrict__ Wg, int Kpad, int Kreal,
    float* Wsm, int tid, int ty, int tx)
{
    #pragma unroll 1
    for (int k0 = 0; k0 < Kpad; k0 += 8) {
        __syncthreads();
        constexpr int PER = (8*TN)/256;
        #pragma unroll
        for (int v = 0; v < PER/4; v++) {
            int e = tid*PER + v*4;
            int k = k0 + e / TN;
            float4 val = make_float4(0.f, 0.f, 0.f, 0.f);
            if (k < Kreal) val = *(const float4*)(Wg + k*TN + (e & (TN-1)));
            *(float4*)(Wsm + e) = val;
        }
        __syncthreads();
        #pragma unroll
        for (int kk = 0; kk < 8; kk++) {
            float bv[8];
            *(float4*)(bv)     = *(const float4*)(Wsm + kk*TN + tx*8);
            *(float4*)(bv + 4) = *(const float4*)(Wsm + kk*TN + tx*8 + 4);
            #pragma unroll
            for (int rr = 0; rr < 8; rr++) {
                float a = Asm[(ty*8+rr)*astride + k0 + kk];
                #pragma unroll
                for (int cc = 0; cc < 8; cc++)
                    acc[rr][cc] = fmaf(a, bv[cc], acc[rr][cc]);
            }
        }
    }
}
__device__ __forceinline__ void store_relu(float* H, int hs,
    const float bias[8], float acc[8][8], int ty, int tx)
{
    #pragma unroll
    for (int rr = 0; rr < 8; rr++) {
        float4 v0, v1;
        v0.x = fmaxf(acc[rr][0] + bias[0], 0.f);
        v0.y = fmaxf(acc[rr][1] + bias[1], 0.f);
        v0.z = fmaxf(acc[rr][2] + bias[2], 0.f);
        v0.w = fmaxf(acc[rr][3] + bias[3], 0.f);
        v1.x = fmaxf(acc[rr][4] + bias[4], 0.f);
        v1.y = fmaxf(acc[rr][5] + bias[5], 0.f);
        v1.z = fmaxf(acc[rr][6] + bias[6], 0.f);
        v1.w = fmaxf(acc[rr][7] + bias[7], 0.f);
        *(float4*)(H + (ty*8+rr)*hs + tx*8)     = v0;
        *(float4*)(H + (ty*8+rr)*hs + tx*8 + 4) = v1;
    }
}
template<int RED>
__device__ __forceinline__ float warp_red(float v) {
    #pragma unroll
    for (int m = RED; m >= 1; m >>= 1) v += __shfl_xor_sync(0xffffffffu, v, m);
    return v;
}

// ---------------------------------------------------------------------------
// Fused MLP kernel: blocks [0,12) node (FFMA), [12,12+2304) edge (mma.sync tf32)
// ---------------------------------------------------------------------------
__global__ void __launch_bounds__(256, 1)
mlp_kernel(const int* __restrict__ seq, const float* __restrict__ trans,
           const float* __restrict__ nw1, const float* __restrict__ nb1,
           const float* __restrict__ nw2, const float* __restrict__ nb2,
           const float* __restrict__ nw3, const float* __restrict__ nb3,
           const float* __restrict__ ng,  const float* __restrict__ nbt,
           const float* __restrict__ eb1, const float* __restrict__ eb2,
           const float* __restrict__ eb3,
           const float* __restrict__ eg,  const float* __restrict__ ebt,
           float* __restrict__ out)
{
    extern __shared__ float sm[];
    int tid  = threadIdx.x;
    int wid  = tid >> 5;
    int lane = tid & 31;

    if (blockIdx.x < NODE_BLOCKS) {
        // ----------------------------- NODE PATH (FFMA) --------------------
        float* A  = sm;
        float* H1 = A  + 64*NODE_AS;
        float* H2 = H1 + 64*NODE_HS;
        float* W  = H2 + 64*NODE_HS;
        int row0 = blockIdx.x * 64;
        int tx = tid & 31, ty = tid >> 5;

        for (int e = tid; e < 64*NODE_AS; e += 256) {
            int r = e / NODE_AS, k = e - r*NODE_AS;
            A[e] = (k < NODE_IN_K) ? g_node_in[(row0+r)*NODE_IN_K + k] : 0.0f;
        }

        float acc[8][8];
        zero_acc(acc);
        mlp_gemm<256>(acc, A, NODE_AS, nw1, 152, 145, W, tid, ty, tx);
        { float b[8]; ld8(b, nb1 + tx*8); store_relu(H1, NODE_HS, b, acc, ty, tx); }

        zero_acc(acc);
        mlp_gemm<256>(acc, H1, NODE_HS, nw2, 256, 256, W, tid, ty, tx);
        { float b[8]; ld8(b, nb2 + tx*8); store_relu(H2, NODE_HS, b, acc, ty, tx); }

        zero_acc(acc);
        mlp_gemm<256>(acc, H2, NODE_HS, nw3, 256, 256, W, tid, ty, tx);

        float b3[8], gv[8], btv[8];
        ld8(b3, nb3 + tx*8); ld8(gv, ng + tx*8); ld8(btv, nbt + tx*8);
        #pragma unroll
        for (int rr = 0; rr < 8; rr++) {
            float v[8], s = 0.f;
            #pragma unroll
            for (int cc = 0; cc < 8; cc++) { v[cc] = acc[rr][cc] + b3[cc]; s += v[cc]; }
            s = warp_red<16>(s);
            float mu = s * (1.0f/256.0f);
            float q = 0.f;
            #pragma unroll
            for (int cc = 0; cc < 8; cc++) { float d = v[cc]-mu; q += d*d; }
            q = warp_red<16>(q);
            float rstd = rsqrtf(q * (1.0f/256.0f) + 1e-5f);
            float o[8];
            #pragma unroll
            for (int cc = 0; cc < 8; cc++) o[cc] = (v[cc]-mu)*rstd*gv[cc] + btv[cc];
            float* op = out + (size_t)(row0 + ty*8 + rr)*CS + tx*8;
            *(float4*)op       = *(float4*)o;
            *(float4*)(op + 4) = *(float4*)(o + 4);
        }
        return;
    }

    // ----------------------------- EDGE PATH (mma.sync tf32) ---------------
    int ebk = blockIdx.x - NODE_BLOCKS;
    int bi  = ebk / (NN*3);
    int rem = ebk % (NN*3);
    int ii  = rem / 3;
    int j0  = (rem % 3) * 128;

    float* A  = sm;
    float* Bs = sm + A_FLOATS;
    int wr = wid >> 1, wc = wid & 1;

    // prefetch B1 while building A
    cpa(Bs, gB1p, B_FLOATS*4, tid, 256);

    // ---- build edge_in tile [128 j-rows x 200 cols] (fp32) ----
    {
        int r = tid & 127, half = tid >> 7;
        int j = j0 + r;
        const float* pti = g_pt + (size_t)(bi*NN + ii)*73;
        const float* ptj = g_pt + (size_t)(bi*NN + j)*73;
        float* Ar = A + r*SA;
        if (half == 0) {
            for (int k = 0; k < 73; k++)  Ar[k] = pti[k];
            for (int k = 73; k < 100; k++) Ar[k] = ptj[k-73];
        } else {
            for (int k = 100; k < 146; k++) Ar[k] = ptj[k-73];
            const float* ti = g_node_in + (size_t)(bi*NN + ii)*NODE_IN_K;
            const float* tj = g_node_in + (size_t)(bi*NN + j)*NODE_IN_K;
            #pragma unroll
            for (int kk = 0; kk < 16; kk++) {
                float si = ti[73+kk], ci = ti[89+kk];
                float sj = tj[73+kk], cj = tj[89+kk];
                Ar[146+kk] = si*cj - ci*sj;
                Ar[162+kk] = ci*cj + si*sj;
            }
            float dx = trans[(bi*NN+ii)*3+0] - trans[(bi*NN+j)*3+0];
            float dy = trans[(bi*NN+ii)*3+1] - trans[(bi*NN+j)*3+1];
            float dz = trans[(bi*NN+ii)*3+2] - trans[(bi*NN+j)*3+2];
            float d = sqrtf(dx*dx + dy*dy + dz*dz);
            const float step = (20.0f - 1e-5f) / 21.0f;
            #pragma unroll
            for (int t = 0; t < 22; t++) {
                float lo = 1e-5f + (float)t * step;
                float up = (t < 21) ? (1e-5f + (float)(t+1)*step) : 1e8f;
                Ar[178+t] = (d > lo && d < up) ? 1.0f : 0.0f;
            }
        }
    }
    CP_WAIT();
    __syncthreads();

    float acc[2][8][4];

    // GEMM1: K=200
    zacc(acc);
    gemm3p<25>(A, Bs, acc, lane, wr, wc);
    __syncthreads();                       // all reads of A and B done
    epi_store(A, eb1, acc, lane, wr, wc);  // H1 -> A[.,0:128]
    cpa(Bs, gB2p, 128*SB*4, tid, 256);
    CP_WAIT();
    __syncthreads();

    // GEMM2: K=128
    zacc(acc);
    gemm3p<16>(A, Bs, acc, lane, wr, wc);
    __syncthreads();
    epi_store(A, eb2, acc, lane, wr, wc);
    cpa(Bs, gB3p, 128*SB*4, tid, 256);
    CP_WAIT();
    __syncthreads();

    // GEMM3: K=128
    zacc(acc);
    gemm3p<16>(A, Bs, acc, lane, wr, wc);

    // ---- bias + LayerNorm + store ----
    int cb = wc*64 + (lane&3)*2;
    int R0 = wr*32 + (lane>>2);
    float sv[4] = {0,0,0,0}, qv[4] = {0,0,0,0};
    #pragma unroll
    for (int nt = 0; nt < 8; nt++){
        float2 bv = *(const float2*)(eb3 + cb + nt*8);
        #pragma unroll
        for (int mt = 0; mt < 2; mt++){
            float v0 = acc[mt][nt][0] + bv.x;
            float v1 = acc[mt][nt][1] + bv.y;
            float v2 = acc[mt][nt][2] + bv.x;
            float v3 = acc[mt][nt][3] + bv.y;
            acc[mt][nt][0]=v0; acc[mt][nt][1]=v1; acc[mt][nt][2]=v2; acc[mt][nt][3]=v3;
            sv[mt*2+0] += v0+v1;       qv[mt*2+0] += v0*v0+v1*v1;
            sv[mt*2+1] += v2+v3;       qv[mt*2+1] += v2*v2+v3*v3;
        }
    }
    #pragma unroll
    for (int s4 = 0; s4 < 4; s4++){
        sv[s4] += __shfl_xor_sync(0xffffffffu, sv[s4], 1);
        sv[s4] += __shfl_xor_sync(0xffffffffu, sv[s4], 2);
        qv[s4] += __shfl_xor_sync(0xffffffffu, qv[s4], 1);
        qv[s4] += __shfl_xor_sync(0xffffffffu, qv[s4], 2);
    }
    float2* red = (float2*)(sm + RED_OFF);
    if ((lane & 3) == 0){
        #pragma unroll
        for (int mt = 0; mt < 2; mt++)
            #pragma unroll
            for (int h = 0; h < 2; h++)
                red[wc*128 + R0 + mt*16 + h*8] = make_float2(sv[mt*2+h], qv[mt*2+h]);
    }
    __syncthreads();
    float mu[4], rs[4];
    #pragma unroll
    for (int mt = 0; mt < 2; mt++)
        #pragma unroll
        for (int h = 0; h < 2; h++){
            int row = R0 + mt*16 + h*8;
            float2 p0 = red[row], p1 = red[128 + row];
            float S = p0.x + p1.x, Q = p0.y + p1.y;
            float m = S * (1.0f/128.0f);
            float var = Q * (1.0f/128.0f) - m*m;
            mu[mt*2+h] = m;
            rs[mt*2+h] = rsqrtf(fmaxf(var, 0.f) + 1e-5f);
        }
    float* oe = out + NODE_ELEMS + ((size_t)(bi*NN + ii)*NN + j0)*CZ;
    #pragma unroll
    for (int nt = 0; nt < 8; nt++){
        float2 g2 = *(const float2*)(eg  + cb + nt*8);
        float2 t2 = *(const float2*)(ebt + cb + nt*8);
        #pragma unroll
        for (int mt = 0; mt < 2; mt++)
            #pragma unroll
            for (int h = 0; h < 2; h++){
                int row = R0 + mt*16 + h*8;
                int s4 = mt*2 + h;
                float va = acc[mt][nt][h*2+0], vb = acc[mt][nt][h*2+1];
                float o0 = (va - mu[s4])*rs[s4]*g2.x + t2.x;
                float o1 = (vb - mu[s4])*rs[s4]*g2.y + t2.y;
                *(float2*)(oe + (size_t)row*CZ + cb + nt*8) = make_float2(o0, o1);
            }
    }
}

// ---------------------------------------------------------------------------
extern "C" void kernel_launch(void* const* d_in, const int* in_sizes, int n_in,
                              void* d_out, int out_size)
{
    const float* noised = (const float*)d_in[0];
    const int*   seq    = (const int*)  d_in[1];
    const float* t      = (const float*)d_in[2];
    const float* fmask  = (const float*)d_in[3];
    const float* trans  = (const float*)d_in[5];
    const float* rots   = (const float*)d_in[6];
    const float* atom14 = (const float*)d_in[7];
    const float* nw1 = (const float*)d_in[8];
    const float* nb1 = (const float*)d_in[9];
    const float* nw2 = (const float*)d_in[10];
    const float* nb2 = (const float*)d_in[11];
    const float* nw3 = (const float*)d_in[12];
    const float* nb3 = (const float*)d_in[13];
    const float* ng  = (const float*)d_in[14];
    const float* nbt = (const float*)d_in[15];
    const float* ew1 = (const float*)d_in[16];
    const float* eb1 = (const float*)d_in[17];
    const float* ew2 = (const float*)d_in[18];
    const float* eb2 = (const float*)d_in[19];
    const float* ew3 = (const float*)d_in[20];
    const float* eb3 = (const float*)d_in[21];
    const float* eg  = (const float*)d_in[22];
    const float* ebt = (const float*)d_in[23];
    float* out = (float*)d_out;

    cudaFuncSetAttribute(mlp_kernel,
                         cudaFuncAttributeMaxDynamicSharedMemorySize, SMEM_BYTES);

    feat_kernel<<<6, 128>>>(noised, seq, t, fmask, trans, rots, atom14);
    wprep_kernel<<<64, 256>>>(ew1, ew2, ew3);
    mlp_kernel<<<NODE_BLOCKS + EDGE_BLOCKS, 256, SMEM_BYTES>>>(
        seq, trans,
        nw1, nb1, nw2, nb2, nw3, nb3, ng, nbt,
        eb1, eb2, eb3, eg, ebt,
        out);
}